// round 8
// baseline (speedup 1.0000x reference)
#include <cuda_runtime.h>
#include <math.h>

#define DD 64
#define TWO_PI_F 6.283185307179586f
#define EPS_F 1e-8f
#define NBLK (148 * 8)

// Cold-path Gauss-Jordan scratch: one [64][128] augmented matrix per block.
// Static device array (no runtime allocation). ~38 MB, touched only when
// Sigma is non-diagonal.
__device__ float g_scratch[NBLK][DD][2 * DD];

__device__ __forceinline__ float pinv_recip(float v) {
    return (v != 0.0f) ? (1.0f / v) : 0.0f;  // pinv semantics for diag
}

// ---------------------------------------------------------------------------
// Single fused kernel. Persistent grid (8 CTAs/SM x 148 SMs).
//
// Phase 0 (per thread): prefetch first sample group's 4x LDG.128 — hides the
// per-block prep behind the first DRAM round trip.
// Phase 1 (per block): scan Sigma (16 KB, L2-cached across blocks): off-diag
// check + diagonal gather; shfl-product det; coef = Phi/sqrt(2*pi*det).
// Phase 2 hot (diagonal Sigma): proven R3/R6 body — 4 samples per thread,
// front-batched MLP=4, half-warp owns a group, 4 shfl trees, one STG.128.
// Phase 2 cold (general Sigma): per-block GJ w/ partial pivoting in global
// scratch, then direct quadratic form. Correctness path only.
// ---------------------------------------------------------------------------
__global__ void __launch_bounds__(256, 8)
fused_kernel(const float* __restrict__ x,
             const float* __restrict__ Phi,
             const float* __restrict__ mu,
             const float* __restrict__ Sigma,
             float* __restrict__ out, int N, int ngroups) {
    __shared__ float sdiag[DD];
    __shared__ float s_wprod[2];
    __shared__ int s_offdiag;
    __shared__ float s_coef;
    __shared__ float s_det;
    __shared__ int s_piv;

    int tid = threadIdx.x;
    int lane = tid & 31;
    int wid = tid >> 5;
    int half = lane >> 4;          // 0 or 1
    int sub = lane & 15;           // 16B chunk within sample
    int g0 = ((blockIdx.x * blockDim.x + tid) >> 5) * 2 + half;
    int gstride = (gridDim.x * blockDim.x) >> 4;   // total half-warps

    const float4* xr = reinterpret_cast<const float4*>(x);
    float4 muv = reinterpret_cast<const float4*>(mu)[sub];

    // ---- Phase 0: prefetch first group (outstanding across prep) ----
    float4 xv0, xv1, xv2, xv3;
    bool have0 = (g0 < ngroups);
    if (have0) {
        int base = g0 * 4;
        xv0 = __ldcs(&xr[(size_t)(base + 0) * 16 + sub]);
        xv1 = __ldcs(&xr[(size_t)(base + 1) * 16 + sub]);
        xv2 = __ldcs(&xr[(size_t)(base + 2) * 16 + sub]);
        xv3 = __ldcs(&xr[(size_t)(base + 3) * 16 + sub]);
    }

    // ---- Phase 1: per-block prep ----
    if (tid == 0) s_offdiag = 0;
    __syncthreads();
    {
        const float4* S4 = reinterpret_cast<const float4*>(Sigma);
        int bad = 0;
        #pragma unroll
        for (int q = 0; q < 4; q++) {
            float4 c = __ldg(&S4[tid * 4 + q]);
            int ebase = (tid * 4 + q) * 4;
            float vals[4] = {c.x, c.y, c.z, c.w};
            #pragma unroll
            for (int i = 0; i < 4; i++) {
                int e = ebase + i;
                int r = e >> 6, col = e & 63;
                if (r == col) sdiag[r] = vals[i];
                else if (vals[i] != 0.0f) bad = 1;
            }
        }
        if (bad) atomicOr(&s_offdiag, 1);
    }
    __syncthreads();

    if (!s_offdiag) {
        // det via parallel shfl product over the 64 diagonal entries.
        if (tid < DD) {
            float v = sdiag[tid];
            #pragma unroll
            for (int m = 16; m >= 1; m >>= 1)
                v *= __shfl_xor_sync(0xffffffffu, v, m);
            if (lane == 0) s_wprod[wid] = v;
        }
        __syncthreads();
        if (tid == 0)
            s_coef = Phi[0] / sqrtf(TWO_PI_F * s_wprod[0] * s_wprod[1]);
        __syncthreads();

        float coef = s_coef;
        float4 av;
        av.x = pinv_recip(sdiag[sub * 4 + 0]);
        av.y = pinv_recip(sdiag[sub * 4 + 1]);
        av.z = pinv_recip(sdiag[sub * 4 + 2]);
        av.w = pinv_recip(sdiag[sub * 4 + 3]);

        // ---- Phase 2 hot: peeled first (prefetched) group ----
        if (have0) {
            int base = g0 * 4;
            float p0, p1, p2, p3;
            {
                float d0 = xv0.x - muv.x, d1 = xv0.y - muv.y,
                      d2 = xv0.z - muv.z, d3 = xv0.w - muv.w;
                p0 = av.x * d0 * d0 + av.y * d1 * d1 + av.z * d2 * d2 + av.w * d3 * d3;
            }
            {
                float d0 = xv1.x - muv.x, d1 = xv1.y - muv.y,
                      d2 = xv1.z - muv.z, d3 = xv1.w - muv.w;
                p1 = av.x * d0 * d0 + av.y * d1 * d1 + av.z * d2 * d2 + av.w * d3 * d3;
            }
            {
                float d0 = xv2.x - muv.x, d1 = xv2.y - muv.y,
                      d2 = xv2.z - muv.z, d3 = xv2.w - muv.w;
                p2 = av.x * d0 * d0 + av.y * d1 * d1 + av.z * d2 * d2 + av.w * d3 * d3;
            }
            {
                float d0 = xv3.x - muv.x, d1 = xv3.y - muv.y,
                      d2 = xv3.z - muv.z, d3 = xv3.w - muv.w;
                p3 = av.x * d0 * d0 + av.y * d1 * d1 + av.z * d2 * d2 + av.w * d3 * d3;
            }
            #pragma unroll
            for (int m = 8; m >= 1; m >>= 1) {
                p0 += __shfl_xor_sync(0xffffffffu, p0, m);
                p1 += __shfl_xor_sync(0xffffffffu, p1, m);
                p2 += __shfl_xor_sync(0xffffffffu, p2, m);
                p3 += __shfl_xor_sync(0xffffffffu, p3, m);
            }
            if (sub == 0) {
                float4 r;
                r.x = -__logf(coef * __expf(-0.5f * p0) + EPS_F);
                r.y = -__logf(coef * __expf(-0.5f * p1) + EPS_F);
                r.z = -__logf(coef * __expf(-0.5f * p2) + EPS_F);
                r.w = -__logf(coef * __expf(-0.5f * p3) + EPS_F);
                *reinterpret_cast<float4*>(out + base) = r;
            }
        }

        // ---- Phase 2 hot: remaining groups ----
        for (int g = g0 + gstride; g < ngroups; g += gstride) {
            int base = g * 4;
            float4 v0 = __ldcs(&xr[(size_t)(base + 0) * 16 + sub]);
            float4 v1 = __ldcs(&xr[(size_t)(base + 1) * 16 + sub]);
            float4 v2 = __ldcs(&xr[(size_t)(base + 2) * 16 + sub]);
            float4 v3 = __ldcs(&xr[(size_t)(base + 3) * 16 + sub]);

            float p0, p1, p2, p3;
            {
                float d0 = v0.x - muv.x, d1 = v0.y - muv.y,
                      d2 = v0.z - muv.z, d3 = v0.w - muv.w;
                p0 = av.x * d0 * d0 + av.y * d1 * d1 + av.z * d2 * d2 + av.w * d3 * d3;
            }
            {
                float d0 = v1.x - muv.x, d1 = v1.y - muv.y,
                      d2 = v1.z - muv.z, d3 = v1.w - muv.w;
                p1 = av.x * d0 * d0 + av.y * d1 * d1 + av.z * d2 * d2 + av.w * d3 * d3;
            }
            {
                float d0 = v2.x - muv.x, d1 = v2.y - muv.y,
                      d2 = v2.z - muv.z, d3 = v2.w - muv.w;
                p2 = av.x * d0 * d0 + av.y * d1 * d1 + av.z * d2 * d2 + av.w * d3 * d3;
            }
            {
                float d0 = v3.x - muv.x, d1 = v3.y - muv.y,
                      d2 = v3.z - muv.z, d3 = v3.w - muv.w;
                p3 = av.x * d0 * d0 + av.y * d1 * d1 + av.z * d2 * d2 + av.w * d3 * d3;
            }
            #pragma unroll
            for (int m = 8; m >= 1; m >>= 1) {
                p0 += __shfl_xor_sync(0xffffffffu, p0, m);
                p1 += __shfl_xor_sync(0xffffffffu, p1, m);
                p2 += __shfl_xor_sync(0xffffffffu, p2, m);
                p3 += __shfl_xor_sync(0xffffffffu, p3, m);
            }
            if (sub == 0) {
                float4 r;
                r.x = -__logf(coef * __expf(-0.5f * p0) + EPS_F);
                r.y = -__logf(coef * __expf(-0.5f * p1) + EPS_F);
                r.z = -__logf(coef * __expf(-0.5f * p2) + EPS_F);
                r.w = -__logf(coef * __expf(-0.5f * p3) + EPS_F);
                *reinterpret_cast<float4*>(out + base) = r;
            }
        }

        // Remainder samples (N not divisible by 4): block 0 / thread 0.
        if ((N & 3) && blockIdx.x == 0 && tid == 0) {
            for (int s = ngroups * 4; s < N; s++) {
                const float* xrow = x + (size_t)s * DD;
                float q = 0.0f;
                for (int d = 0; d < DD; d++) {
                    float dv = xrow[d] - mu[d];
                    q += pinv_recip(sdiag[d]) * dv * dv;
                }
                out[s] = -__logf(coef * __expf(-0.5f * q) + EPS_F);
            }
        }
    } else {
        // ---- Phase 2 cold: general Sigma. Per-block GJ in global scratch ----
        float (*aug)[2 * DD] = g_scratch[blockIdx.x];
        for (int i = tid; i < DD * 2 * DD; i += blockDim.x) {
            int r = i / (2 * DD), c = i % (2 * DD);
            aug[r][c] = (c < DD) ? Sigma[r * DD + c]
                                 : ((c - DD == r) ? 1.0f : 0.0f);
        }
        if (tid == 0) s_det = 1.0f;
        __syncthreads();

        for (int k = 0; k < DD; k++) {
            if (tid == 0) {
                int p = k;
                float best = fabsf(aug[k][k]);
                for (int r = k + 1; r < DD; r++) {
                    float v = fabsf(aug[r][k]);
                    if (v > best) { best = v; p = r; }
                }
                s_piv = p;
                if (p != k) s_det = -s_det;
            }
            __syncthreads();
            int p = s_piv;
            if (p != k) {
                for (int c = tid; c < 2 * DD; c += blockDim.x) {
                    float t = aug[k][c];
                    aug[k][c] = aug[p][c];
                    aug[p][c] = t;
                }
                __syncthreads();
            }
            float piv = aug[k][k];
            if (tid == 0) s_det *= piv;
            float inv_piv = (piv != 0.0f) ? 1.0f / piv : 0.0f;
            for (int c = tid; c < 2 * DD; c += blockDim.x)
                aug[k][c] *= inv_piv;
            __syncthreads();
            for (int i = tid; i < DD * 2 * DD; i += blockDim.x) {
                int r = i / (2 * DD), c = i % (2 * DD);
                if (r != k) {
                    float f = aug[r][k] * ((c == k) ? 0.0f : 1.0f);
                    // standard elimination: row r -= aug[r][k] * row k, with
                    // column k handled so aug[r][k] -> 0 exactly
                    aug[r][c] = (c == k) ? 0.0f
                                         : aug[r][c] - aug[r][k] * aug[k][c];
                    (void)f;
                }
            }
            __syncthreads();
        }

        if (tid == 0)
            s_coef = Phi[0] / sqrtf(TWO_PI_F * s_det);
        __syncthreads();
        float coef = s_coef;

        // Quadratic form per sample; invA = aug[.][DD..2DD) (L2-cached).
        if (sub == 0) {
            for (int g = g0; g < ngroups; g += gstride) {
                int base = g * 4;
                for (int j = 0; j < 4; j++) {
                    int s = base + j;
                    if (s >= N) break;
                    const float* xrow = x + (size_t)s * DD;
                    float q = 0.0f;
#pragma unroll 1
                    for (int e = 0; e < DD; e++) {
                        float de = xrow[e] - mu[e];
                        float t = 0.0f;
#pragma unroll 8
                        for (int d = 0; d < DD; d++)
                            t += aug[e][DD + d] * (xrow[d] - mu[d]);
                        q += de * t;
                    }
                    out[s] = -__logf(coef * __expf(-0.5f * q) + EPS_F);
                }
            }
        }
        if ((N & 3) && blockIdx.x == 0 && tid == 0) {
            for (int s = ngroups * 4; s < N; s++) {
                const float* xrow = x + (size_t)s * DD;
                float q = 0.0f;
                for (int e = 0; e < DD; e++) {
                    float de = xrow[e] - mu[e];
                    float t = 0.0f;
                    for (int d = 0; d < DD; d++)
                        t += aug[e][DD + d] * (xrow[d] - mu[d]);
                    q += de * t;
                }
                out[s] = -__logf(coef * __expf(-0.5f * q) + EPS_F);
            }
        }
    }
}

extern "C" void kernel_launch(void* const* d_in, const int* in_sizes, int n_in,
                              void* d_out, int out_size) {
    const float* samples = (const float*)d_in[0];
    const float* Phi     = (const float*)d_in[1];
    const float* mu      = (const float*)d_in[2];
    const float* Sigma   = (const float*)d_in[3];
    int N = out_size;  // one output per sample

    int ngroups = N >> 2;   // full 4-sample groups
    fused_kernel<<<NBLK, 256>>>(samples, Phi, mu, Sigma,
                                (float*)d_out, N, ngroups);
}

// round 9
// speedup vs baseline: 1.0811x; 1.0811x over previous
#include <cuda_runtime.h>
#include <math.h>

#define DD 64
#define TWO_PI_F 6.283185307179586f
#define EPS_F 1e-8f

// Device-side scratch (no allocations allowed).
__device__ __align__(16) float g_diag[DD];
__device__ float g_invA[DD * DD];
__device__ float g_coef;
__device__ int g_isdiag;

// ---------------------------------------------------------------------------
// Prep kernel (R6-proven lean version). Diag fast path: vectorized float4
// scan (off-diag check + diag gather in one pass), shfl-product det.
// General path: Gauss-Jordan w/ partial pivoting. 1 block, 256 threads.
// Signals dependent launch (PDL) as soon as g_* are published.
// ---------------------------------------------------------------------------
__global__ void prep_kernel(const float* __restrict__ Sigma,
                            const float* __restrict__ Phi) {
    __shared__ float aug[DD][2 * DD];
    __shared__ float colk[DD];
    __shared__ float sdiag[DD];
    __shared__ float s_wprod[2];
    __shared__ int s_offdiag;
    __shared__ float s_det;
    __shared__ int s_piv;
    int tid = threadIdx.x;
    int lane = tid & 31;
    int wid = tid >> 5;

    if (tid == 0) s_offdiag = 0;
    __syncthreads();

    // One vectorized pass over Sigma: 1024 float4, 256 threads x 4 each.
    {
        const float4* S4 = reinterpret_cast<const float4*>(Sigma);
        float4 c0 = S4[tid * 4 + 0];
        float4 c1 = S4[tid * 4 + 1];
        float4 c2 = S4[tid * 4 + 2];
        float4 c3 = S4[tid * 4 + 3];
        int bad = 0;
        #pragma unroll
        for (int q = 0; q < 4; q++) {
            float4 c = (q == 0) ? c0 : (q == 1) ? c1 : (q == 2) ? c2 : c3;
            int ebase = (tid * 4 + q) * 4;
            float vals[4] = {c.x, c.y, c.z, c.w};
            #pragma unroll
            for (int i = 0; i < 4; i++) {
                int e = ebase + i;
                int r = e >> 6, col = e & 63;
                if (r == col) sdiag[r] = vals[i];
                else if (vals[i] != 0.0f) bad = 1;
            }
        }
        if (bad) atomicOr(&s_offdiag, 1);
    }
    __syncthreads();

    if (!s_offdiag) {
        if (tid < DD) {
            float v = sdiag[tid];
            g_diag[tid] = (v != 0.0f) ? 1.0f / v : 0.0f;  // pinv semantics
        }
        if (tid < DD) {
            float v = sdiag[tid];
            #pragma unroll
            for (int m = 16; m >= 1; m >>= 1)
                v *= __shfl_xor_sync(0xffffffffu, v, m);
            if (lane == 0) s_wprod[wid] = v;
        }
        __syncthreads();
        if (tid == 0) {
            float det = s_wprod[0] * s_wprod[1];
            g_coef = Phi[0] / sqrtf(TWO_PI_F * det);
            g_isdiag = 1;
        }
        // Publish g_* to the dependent grid, then allow it to proceed.
        __threadfence();
        __syncthreads();
        asm volatile("griddepcontrol.launch_dependents;" ::: "memory");
        return;
    }

    // --- General path: Gauss-Jordan with partial pivoting on [Sigma | I] ---
    for (int i = tid; i < DD * 2 * DD; i += blockDim.x) {
        int r = i / (2 * DD), c = i % (2 * DD);
        aug[r][c] = (c < DD) ? Sigma[r * DD + c]
                             : ((c - DD == r) ? 1.0f : 0.0f);
    }
    if (tid == 0) s_det = 1.0f;
    __syncthreads();

    for (int k = 0; k < DD; k++) {
        if (tid == 0) {
            int p = k;
            float best = fabsf(aug[k][k]);
            for (int r = k + 1; r < DD; r++) {
                float v = fabsf(aug[r][k]);
                if (v > best) { best = v; p = r; }
            }
            s_piv = p;
            if (p != k) s_det = -s_det;
        }
        __syncthreads();
        int p = s_piv;
        if (p != k) {
            for (int c = tid; c < 2 * DD; c += blockDim.x) {
                float t = aug[k][c];
                aug[k][c] = aug[p][c];
                aug[p][c] = t;
            }
            __syncthreads();
        }
        float piv = aug[k][k];
        if (tid == 0) s_det *= piv;
        float inv_piv = (piv != 0.0f) ? 1.0f / piv : 0.0f;
        for (int c = tid; c < 2 * DD; c += blockDim.x) {
            aug[k][c] *= inv_piv;
        }
        if (tid < DD) colk[tid] = (tid == k) ? 0.0f : aug[tid][k];
        __syncthreads();
        for (int i = tid; i < DD * 2 * DD; i += blockDim.x) {
            int r = i / (2 * DD), c = i % (2 * DD);
            if (r != k) aug[r][c] -= colk[r] * aug[k][c];
        }
        __syncthreads();
    }

    for (int i = tid; i < DD * DD; i += blockDim.x) {
        int r = i >> 6, c = i & 63;
        g_invA[i] = aug[r][DD + c];
    }
    if (tid == 0) {
        g_coef = Phi[0] / sqrtf(TWO_PI_F * s_det);
        g_isdiag = 0;
    }
    __threadfence();
    __syncthreads();
    asm volatile("griddepcontrol.launch_dependents;" ::: "memory");
}

// ---------------------------------------------------------------------------
// Main kernel (diag fast path): R6-proven config. 4 samples per thread,
// 4 front-batched __ldcs LDG.128 (MLP_p1=4) issued BEFORE the PDL wait so
// they overlap prep's execution; 32 regs, 8 CTAs/SM. Half-warp owns a
// 4-sample group; 4 shfl trees; lane sub==0 writes one STG.128.
// ---------------------------------------------------------------------------
__global__ void __launch_bounds__(256, 8)
density_kernel(const float* __restrict__ x,
               const float* __restrict__ mu,
               float* __restrict__ out, int N) {
    int lane = threadIdx.x & 31;
    int warp_g = (blockIdx.x * blockDim.x + threadIdx.x) >> 5;
    int half = lane >> 4;          // 0 or 1
    int sub = lane & 15;           // 16B chunk within sample
    int base = warp_g * 8 + half * 4;   // first of this thread's 4 samples
    if (base >= N) return;

    // ---- Independent prologue: loads of x and mu don't depend on prep ----
    const float4* xr = reinterpret_cast<const float4*>(x);
    float4 xv0 = __ldcs(&xr[(size_t)(base + 0) * 16 + sub]);
    float4 xv1 = __ldcs(&xr[(size_t)(base + 1) * 16 + sub]);
    float4 xv2 = __ldcs(&xr[(size_t)(base + 2) * 16 + sub]);
    float4 xv3 = __ldcs(&xr[(size_t)(base + 3) * 16 + sub]);
    float4 muv = reinterpret_cast<const float4*>(mu)[sub];

    // ---- Wait for prep's published results (PDL) ----
    asm volatile("griddepcontrol.wait;" ::: "memory");

    if (g_isdiag) {
        float4 av = reinterpret_cast<const float4*>(g_diag)[sub];

        float p0, p1, p2, p3;
        {
            float d0 = xv0.x - muv.x, d1 = xv0.y - muv.y,
                  d2 = xv0.z - muv.z, d3 = xv0.w - muv.w;
            p0 = av.x * d0 * d0 + av.y * d1 * d1 + av.z * d2 * d2 + av.w * d3 * d3;
        }
        {
            float d0 = xv1.x - muv.x, d1 = xv1.y - muv.y,
                  d2 = xv1.z - muv.z, d3 = xv1.w - muv.w;
            p1 = av.x * d0 * d0 + av.y * d1 * d1 + av.z * d2 * d2 + av.w * d3 * d3;
        }
        {
            float d0 = xv2.x - muv.x, d1 = xv2.y - muv.y,
                  d2 = xv2.z - muv.z, d3 = xv2.w - muv.w;
            p2 = av.x * d0 * d0 + av.y * d1 * d1 + av.z * d2 * d2 + av.w * d3 * d3;
        }
        {
            float d0 = xv3.x - muv.x, d1 = xv3.y - muv.y,
                  d2 = xv3.z - muv.z, d3 = xv3.w - muv.w;
            p3 = av.x * d0 * d0 + av.y * d1 * d1 + av.z * d2 * d2 + av.w * d3 * d3;
        }

        // 4 independent 16-lane reduction trees (masks < 16 keep halves
        // separate).
        #pragma unroll
        for (int m = 8; m >= 1; m >>= 1) {
            p0 += __shfl_xor_sync(0xffffffffu, p0, m);
            p1 += __shfl_xor_sync(0xffffffffu, p1, m);
            p2 += __shfl_xor_sync(0xffffffffu, p2, m);
            p3 += __shfl_xor_sync(0xffffffffu, p3, m);
        }

        if (sub == 0) {
            float coef = g_coef;
            float4 r;
            r.x = -__logf(coef * __expf(-0.5f * p0) + EPS_F);
            r.y = -__logf(coef * __expf(-0.5f * p1) + EPS_F);
            r.z = -__logf(coef * __expf(-0.5f * p2) + EPS_F);
            r.w = -__logf(coef * __expf(-0.5f * p3) + EPS_F);
            *reinterpret_cast<float4*>(out + base) = r;
        }
    } else {
        // General quadratic form (cold path).
        if (sub == 0) {
            for (int j = 0; j < 4; j++) {
                int s = base + j;
                if (s >= N) break;
                const float* xrow = x + (size_t)s * DD;
                float q = 0.0f;
#pragma unroll 1
                for (int e = 0; e < DD; e++) {
                    float de = xrow[e] - mu[e];
                    float t = 0.0f;
#pragma unroll 8
                    for (int d = 0; d < DD; d++)
                        t += g_invA[e * DD + d] * (xrow[d] - mu[d]);
                    q += de * t;
                }
                float dens = g_coef * __expf(-0.5f * q);
                out[s] = -__logf(dens + EPS_F);
            }
        }
    }
}

extern "C" void kernel_launch(void* const* d_in, const int* in_sizes, int n_in,
                              void* d_out, int out_size) {
    const float* samples = (const float*)d_in[0];
    const float* Phi     = (const float*)d_in[1];
    const float* mu      = (const float*)d_in[2];
    const float* Sigma   = (const float*)d_in[3];
    int N = out_size;  // one output per sample

    prep_kernel<<<1, 256>>>(Sigma, Phi);

    // Density launched with PDL so its prologue (x loads) overlaps prep.
    long long total = (long long)N * 4;   // 4 samples/thread, 16 lanes/sample
    int threads = 256;
    int blocks = (int)((total + threads - 1) / threads);

    cudaLaunchConfig_t cfg = {};
    cfg.gridDim = dim3(blocks, 1, 1);
    cfg.blockDim = dim3(threads, 1, 1);
    cfg.dynamicSmemBytes = 0;
    cfg.stream = 0;
    cudaLaunchAttribute attrs[1];
    attrs[0].id = cudaLaunchAttributeProgrammaticStreamSerialization;
    attrs[0].val.programmaticStreamSerializationAllowed = 1;
    cfg.attrs = attrs;
    cfg.numAttrs = 1;

    cudaLaunchKernelEx(&cfg, density_kernel, samples, mu, (float*)d_out, N);
}

// round 10
// speedup vs baseline: 1.0948x; 1.0126x over previous
#include <cuda_runtime.h>
#include <math.h>

#define DD 64
#define TWO_PI_F 6.283185307179586f
#define EPS_F 1e-8f

// Device-side scratch (no allocations allowed).
__device__ __align__(16) float g_diag[DD];
__device__ float g_invA[DD * DD];
__device__ float g_coef;
__device__ int g_isdiag;

// ---------------------------------------------------------------------------
// Prep kernel. Fires PDL launch_dependents at ENTRY so the density grid
// launches and runs its independent prologue (sample loads) concurrently
// with this kernel's entire execution. density's griddepcontrol.wait gates
// on this kernel's completion (+ implicit memory visibility), so g_* are
// safely published regardless of trigger position.
// Diag fast path: vectorized float4 scan (off-diag check + diag gather),
// shfl-product det. General path: Gauss-Jordan w/ partial pivoting.
// ---------------------------------------------------------------------------
__global__ void prep_kernel(const float* __restrict__ Sigma,
                            const float* __restrict__ Phi) {
    // Let the dependent grid launch NOW — maximum overlap.
    asm volatile("griddepcontrol.launch_dependents;" ::: "memory");

    __shared__ float aug[DD][2 * DD];
    __shared__ float colk[DD];
    __shared__ float sdiag[DD];
    __shared__ float s_wprod[2];
    __shared__ int s_offdiag;
    __shared__ float s_det;
    __shared__ int s_piv;
    int tid = threadIdx.x;
    int lane = tid & 31;
    int wid = tid >> 5;

    if (tid == 0) s_offdiag = 0;
    __syncthreads();

    // One vectorized pass over Sigma: 1024 float4, 256 threads x 4 each.
    {
        const float4* S4 = reinterpret_cast<const float4*>(Sigma);
        float4 c0 = S4[tid * 4 + 0];
        float4 c1 = S4[tid * 4 + 1];
        float4 c2 = S4[tid * 4 + 2];
        float4 c3 = S4[tid * 4 + 3];
        int bad = 0;
        #pragma unroll
        for (int q = 0; q < 4; q++) {
            float4 c = (q == 0) ? c0 : (q == 1) ? c1 : (q == 2) ? c2 : c3;
            int ebase = (tid * 4 + q) * 4;
            float vals[4] = {c.x, c.y, c.z, c.w};
            #pragma unroll
            for (int i = 0; i < 4; i++) {
                int e = ebase + i;
                int r = e >> 6, col = e & 63;
                if (r == col) sdiag[r] = vals[i];
                else if (vals[i] != 0.0f) bad = 1;
            }
        }
        if (bad) atomicOr(&s_offdiag, 1);
    }
    __syncthreads();

    if (!s_offdiag) {
        if (tid < DD) {
            float v = sdiag[tid];
            g_diag[tid] = (v != 0.0f) ? 1.0f / v : 0.0f;  // pinv semantics
        }
        if (tid < DD) {
            float v = sdiag[tid];
            #pragma unroll
            for (int m = 16; m >= 1; m >>= 1)
                v *= __shfl_xor_sync(0xffffffffu, v, m);
            if (lane == 0) s_wprod[wid] = v;
        }
        __syncthreads();
        if (tid == 0) {
            float det = s_wprod[0] * s_wprod[1];
            g_coef = Phi[0] / sqrtf(TWO_PI_F * det);
            g_isdiag = 1;
        }
        return;  // kernel completion publishes g_* to the waiting grid
    }

    // --- General path: Gauss-Jordan with partial pivoting on [Sigma | I] ---
    for (int i = tid; i < DD * 2 * DD; i += blockDim.x) {
        int r = i / (2 * DD), c = i % (2 * DD);
        aug[r][c] = (c < DD) ? Sigma[r * DD + c]
                             : ((c - DD == r) ? 1.0f : 0.0f);
    }
    if (tid == 0) s_det = 1.0f;
    __syncthreads();

    for (int k = 0; k < DD; k++) {
        if (tid == 0) {
            int p = k;
            float best = fabsf(aug[k][k]);
            for (int r = k + 1; r < DD; r++) {
                float v = fabsf(aug[r][k]);
                if (v > best) { best = v; p = r; }
            }
            s_piv = p;
            if (p != k) s_det = -s_det;
        }
        __syncthreads();
        int p = s_piv;
        if (p != k) {
            for (int c = tid; c < 2 * DD; c += blockDim.x) {
                float t = aug[k][c];
                aug[k][c] = aug[p][c];
                aug[p][c] = t;
            }
            __syncthreads();
        }
        float piv = aug[k][k];
        if (tid == 0) s_det *= piv;
        float inv_piv = (piv != 0.0f) ? 1.0f / piv : 0.0f;
        for (int c = tid; c < 2 * DD; c += blockDim.x) {
            aug[k][c] *= inv_piv;
        }
        if (tid < DD) colk[tid] = (tid == k) ? 0.0f : aug[tid][k];
        __syncthreads();
        for (int i = tid; i < DD * 2 * DD; i += blockDim.x) {
            int r = i / (2 * DD), c = i % (2 * DD);
            if (r != k) aug[r][c] -= colk[r] * aug[k][c];
        }
        __syncthreads();
    }

    for (int i = tid; i < DD * DD; i += blockDim.x) {
        int r = i >> 6, c = i & 63;
        g_invA[i] = aug[r][DD + c];
    }
    if (tid == 0) {
        g_coef = Phi[0] / sqrtf(TWO_PI_F * s_det);
        g_isdiag = 0;
    }
}

// ---------------------------------------------------------------------------
// Main kernel (diag fast path): proven config. 4 samples per thread,
// 4 front-batched __ldcs LDG.128 (MLP_p1=4) issued BEFORE the PDL wait so
// they overlap prep's execution; 32 regs, 8 CTAs/SM. Half-warp owns a
// 4-sample group; 4 shfl trees; lane sub==0 writes one STG.128.
// ---------------------------------------------------------------------------
__global__ void __launch_bounds__(256, 8)
density_kernel(const float* __restrict__ x,
               const float* __restrict__ mu,
               float* __restrict__ out, int N) {
    int lane = threadIdx.x & 31;
    int warp_g = (blockIdx.x * blockDim.x + threadIdx.x) >> 5;
    int half = lane >> 4;          // 0 or 1
    int sub = lane & 15;           // 16B chunk within sample
    int base = warp_g * 8 + half * 4;   // first of this thread's 4 samples
    if (base >= N) return;

    // ---- Independent prologue: loads of x and mu don't depend on prep ----
    const float4* xr = reinterpret_cast<const float4*>(x);
    float4 xv0 = __ldcs(&xr[(size_t)(base + 0) * 16 + sub]);
    float4 xv1 = __ldcs(&xr[(size_t)(base + 1) * 16 + sub]);
    float4 xv2 = __ldcs(&xr[(size_t)(base + 2) * 16 + sub]);
    float4 xv3 = __ldcs(&xr[(size_t)(base + 3) * 16 + sub]);
    float4 muv = reinterpret_cast<const float4*>(mu)[sub];

    // ---- Wait for prep grid completion (publishes g_*) ----
    asm volatile("griddepcontrol.wait;" ::: "memory");

    if (g_isdiag) {
        float4 av = reinterpret_cast<const float4*>(g_diag)[sub];

        float p0, p1, p2, p3;
        {
            float d0 = xv0.x - muv.x, d1 = xv0.y - muv.y,
                  d2 = xv0.z - muv.z, d3 = xv0.w - muv.w;
            p0 = av.x * d0 * d0 + av.y * d1 * d1 + av.z * d2 * d2 + av.w * d3 * d3;
        }
        {
            float d0 = xv1.x - muv.x, d1 = xv1.y - muv.y,
                  d2 = xv1.z - muv.z, d3 = xv1.w - muv.w;
            p1 = av.x * d0 * d0 + av.y * d1 * d1 + av.z * d2 * d2 + av.w * d3 * d3;
        }
        {
            float d0 = xv2.x - muv.x, d1 = xv2.y - muv.y,
                  d2 = xv2.z - muv.z, d3 = xv2.w - muv.w;
            p2 = av.x * d0 * d0 + av.y * d1 * d1 + av.z * d2 * d2 + av.w * d3 * d3;
        }
        {
            float d0 = xv3.x - muv.x, d1 = xv3.y - muv.y,
                  d2 = xv3.z - muv.z, d3 = xv3.w - muv.w;
            p3 = av.x * d0 * d0 + av.y * d1 * d1 + av.z * d2 * d2 + av.w * d3 * d3;
        }

        // 4 independent 16-lane reduction trees (masks < 16 keep halves
        // separate).
        #pragma unroll
        for (int m = 8; m >= 1; m >>= 1) {
            p0 += __shfl_xor_sync(0xffffffffu, p0, m);
            p1 += __shfl_xor_sync(0xffffffffu, p1, m);
            p2 += __shfl_xor_sync(0xffffffffu, p2, m);
            p3 += __shfl_xor_sync(0xffffffffu, p3, m);
        }

        if (sub == 0) {
            float coef = g_coef;
            float4 r;
            r.x = -__logf(coef * __expf(-0.5f * p0) + EPS_F);
            r.y = -__logf(coef * __expf(-0.5f * p1) + EPS_F);
            r.z = -__logf(coef * __expf(-0.5f * p2) + EPS_F);
            r.w = -__logf(coef * __expf(-0.5f * p3) + EPS_F);
            *reinterpret_cast<float4*>(out + base) = r;
        }
    } else {
        // General quadratic form (cold path).
        if (sub == 0) {
            for (int j = 0; j < 4; j++) {
                int s = base + j;
                if (s >= N) break;
                const float* xrow = x + (size_t)s * DD;
                float q = 0.0f;
#pragma unroll 1
                for (int e = 0; e < DD; e++) {
                    float de = xrow[e] - mu[e];
                    float t = 0.0f;
#pragma unroll 8
                    for (int d = 0; d < DD; d++)
                        t += g_invA[e * DD + d] * (xrow[d] - mu[d]);
                    q += de * t;
                }
                float dens = g_coef * __expf(-0.5f * q);
                out[s] = -__logf(dens + EPS_F);
            }
        }
    }
}

extern "C" void kernel_launch(void* const* d_in, const int* in_sizes, int n_in,
                              void* d_out, int out_size) {
    const float* samples = (const float*)d_in[0];
    const float* Phi     = (const float*)d_in[1];
    const float* mu      = (const float*)d_in[2];
    const float* Sigma   = (const float*)d_in[3];
    int N = out_size;  // one output per sample

    prep_kernel<<<1, 256>>>(Sigma, Phi);

    // Density launched with PDL; its prologue overlaps prep's execution.
    long long total = (long long)N * 4;   // 4 samples/thread, 16 lanes/sample
    int threads = 256;
    int blocks = (int)((total + threads - 1) / threads);

    cudaLaunchConfig_t cfg = {};
    cfg.gridDim = dim3(blocks, 1, 1);
    cfg.blockDim = dim3(threads, 1, 1);
    cfg.dynamicSmemBytes = 0;
    cfg.stream = 0;
    cudaLaunchAttribute attrs[1];
    attrs[0].id = cudaLaunchAttributeProgrammaticStreamSerialization;
    attrs[0].val.programmaticStreamSerializationAllowed = 1;
    cfg.attrs = attrs;
    cfg.numAttrs = 1;

    cudaLaunchKernelEx(&cfg, density_kernel, samples, mu, (float*)d_out, N);
}